// round 1
// baseline (speedup 1.0000x reference)
#include <cuda_runtime.h>
#include <cuda_bf16.h>

// SurfNetwork: fused gather + sigmoid + tiny MLP + transmittance scan + rgb reduce.
// One block per ray (B blocks), one thread per sample (N=128 threads).
//
// Inputs (metadata order):
//   d_in[0] x          int32  [B, N, 2]   hash-grid indices
//   d_in[1] d          f32    [B, 16]     view direction encoding (per ray)
//   d_in[2] gridWeight f32    [TABLE, 4]  feature table (256 MB)
//   d_in[3] W0         f32    [22, 8]
//   d_in[4] W1         f32    [8, 3]
// Output: d_out = [ sigma (B*N f32) | rgb (B*3 f32) ]

__device__ __forceinline__ float fast_sigmoid(float z) {
    return 1.0f / (1.0f + __expf(-z));
}

__global__ __launch_bounds__(128) void surfnet_kernel(
    const int*   __restrict__ x,      // [B, N, 2]
    const float* __restrict__ dvec,   // [B, 16]
    const float* __restrict__ grid,   // [TABLE, 4]
    const float* __restrict__ W0,     // [22, 8] row-major (in, out)
    const float* __restrict__ W1,     // [8, 3]  row-major (in, out)
    float*       __restrict__ sigma_out, // [B, N]
    float*       __restrict__ rgb_out,   // [B, 3]
    int N)
{
    const int b    = blockIdx.x;
    const int tid  = threadIdx.x;
    const int lane = tid & 31;
    const int wid  = tid >> 5;
    const int nwarps = blockDim.x >> 5;

    __shared__ float sW0g[48];   // W0 rows 16..21 (geo part), [6][8]
    __shared__ float sW1[24];    // [8][3]
    __shared__ float sBase[8];   // d[b] @ W0[0:16,:]  (shared across all samples of ray)
    __shared__ float sWprod[8];  // per-warp inclusive products for the scan
    __shared__ float sRacc[3][8];

    // ---- per-block setup (blockDim >= 80 for this problem; N = 128) ----
    if (tid < 48) {
        int r = tid >> 3, c = tid & 7;
        sW0g[tid] = W0[(16 + r) * 8 + c];
    } else if (tid < 72) {
        sW1[tid - 48] = W1[tid - 48];
    } else if (tid < 80) {
        int j = tid - 72;
        float s = 0.0f;
        const float* dv = dvec + (size_t)b * 16;
        #pragma unroll
        for (int i = 0; i < 16; i++) s = fmaf(dv[i], W0[i * 8 + j], s);
        sBase[j] = s;
    }
    __syncthreads();

    // ---- gather two feature rows (the hot random-access path) ----
    const int2 idx = ((const int2*)x)[(size_t)b * N + tid];
    const float4 f0 = __ldg((const float4*)grid + idx.x);
    const float4 f1 = __ldg((const float4*)grid + idx.y);

    const float sg = fast_sigmoid(f0.x * f1.x);
    sigma_out[(size_t)b * N + tid] = sg;

    // ---- tiny MLP: h = relu(base + geo @ W0[16:22,:]); color = sigmoid(h @ W1) ----
    float h[8];
    #pragma unroll
    for (int j = 0; j < 8; j++) {
        float v = sBase[j];
        v = fmaf(f0.y, sW0g[0 * 8 + j], v);
        v = fmaf(f0.z, sW0g[1 * 8 + j], v);
        v = fmaf(f0.w, sW0g[2 * 8 + j], v);
        v = fmaf(f1.y, sW0g[3 * 8 + j], v);
        v = fmaf(f1.z, sW0g[4 * 8 + j], v);
        v = fmaf(f1.w, sW0g[5 * 8 + j], v);
        h[j] = fmaxf(v, 0.0f);
    }
    float c0 = 0.f, c1 = 0.f, c2 = 0.f;
    #pragma unroll
    for (int j = 0; j < 8; j++) {
        c0 = fmaf(h[j], sW1[j * 3 + 0], c0);
        c1 = fmaf(h[j], sW1[j * 3 + 1], c1);
        c2 = fmaf(h[j], sW1[j * 3 + 2], c2);
    }
    c0 = fast_sigmoid(c0);
    c1 = fast_sigmoid(c1);
    c2 = fast_sigmoid(c2);

    // ---- exclusive product scan of (1 - sigma) along the ray ----
    float incl = 1.0f - sg;
    #pragma unroll
    for (int off = 1; off < 32; off <<= 1) {
        float v = __shfl_up_sync(0xFFFFFFFFu, incl, off);
        if (lane >= off) incl *= v;
    }
    float excl = __shfl_up_sync(0xFFFFFFFFu, incl, 1);
    if (lane == 0) excl = 1.0f;
    if (lane == 31) sWprod[wid] = incl;
    __syncthreads();

    float prefix = 1.0f;
    #pragma unroll 4
    for (int w = 0; w < wid; w++) prefix *= sWprod[w];

    const float T = prefix * excl;   // transmittance before this sample
    const float wgt = T * sg;

    // ---- weighted rgb reduction over the ray ----
    float r0 = wgt * c0, r1 = wgt * c1, r2 = wgt * c2;
    #pragma unroll
    for (int off = 16; off > 0; off >>= 1) {
        r0 += __shfl_down_sync(0xFFFFFFFFu, r0, off);
        r1 += __shfl_down_sync(0xFFFFFFFFu, r1, off);
        r2 += __shfl_down_sync(0xFFFFFFFFu, r2, off);
    }
    if (lane == 0) {
        sRacc[0][wid] = r0;
        sRacc[1][wid] = r1;
        sRacc[2][wid] = r2;
    }
    __syncthreads();

    if (tid == 0) {
        float s0 = 0.f, s1 = 0.f, s2 = 0.f;
        for (int w = 0; w < nwarps; w++) {
            s0 += sRacc[0][w];
            s1 += sRacc[1][w];
            s2 += sRacc[2][w];
        }
        float* rb = rgb_out + (size_t)b * 3;
        rb[0] = s0; rb[1] = s1; rb[2] = s2;
    }
}

extern "C" void kernel_launch(void* const* d_in, const int* in_sizes, int n_in,
                              void* d_out, int out_size)
{
    const int*   x    = (const int*)d_in[0];
    const float* dv   = (const float*)d_in[1];
    const float* grid = (const float*)d_in[2];
    const float* W0   = (const float*)d_in[3];
    const float* W1   = (const float*)d_in[4];

    const int BN = in_sizes[0] / 2;   // B*N
    const int B  = in_sizes[1] / 16;  // rays
    const int N  = BN / B;            // samples per ray (128)

    float* sigma_out = (float*)d_out;
    float* rgb_out   = sigma_out + (size_t)BN;

    surfnet_kernel<<<B, N>>>(x, dv, grid, W0, W1, sigma_out, rgb_out, N);
}

// round 4
// speedup vs baseline: 1.0009x; 1.0009x over previous
#include <cuda_runtime.h>
#include <cuda_bf16.h>

// SurfNetwork fused kernel, warp-per-ray version.
// B rays, N=128 samples/ray. One warp handles one ray: 4 consecutive samples
// per lane -> 8 independent float4 gathers in flight per thread, no block
// barriers on the hot path (warp-shuffle product scan + reduce).
//
// Inputs (metadata order):
//   d_in[0] x          int32  [B, N, 2]
//   d_in[1] d          f32    [B, 16]
//   d_in[2] gridWeight f32    [TABLE, 4]
//   d_in[3] W0         f32    [22, 8]
//   d_in[4] W1         f32    [8, 3]
// Output: d_out = [ sigma (B*N f32) | rgb (B*3 f32) ]

__device__ __forceinline__ float fast_sigmoid(float z) {
    return 1.0f / (1.0f + __expf(-z));
}

__device__ __forceinline__ void mlp_color(
    const float4 fa, const float4 fb,
    const float* __restrict__ basev,   // [8] regs
    const float* __restrict__ sW0g,    // [6][8] shared
    const float* __restrict__ sW1,     // [8][3] shared
    float& c0, float& c1, float& c2)
{
    float h[8];
    #pragma unroll
    for (int j = 0; j < 8; j++) {
        float v = basev[j];
        v = fmaf(fa.y, sW0g[0 * 8 + j], v);
        v = fmaf(fa.z, sW0g[1 * 8 + j], v);
        v = fmaf(fa.w, sW0g[2 * 8 + j], v);
        v = fmaf(fb.y, sW0g[3 * 8 + j], v);
        v = fmaf(fb.z, sW0g[4 * 8 + j], v);
        v = fmaf(fb.w, sW0g[5 * 8 + j], v);
        h[j] = fmaxf(v, 0.0f);
    }
    c0 = 0.f; c1 = 0.f; c2 = 0.f;
    #pragma unroll
    for (int j = 0; j < 8; j++) {
        c0 = fmaf(h[j], sW1[j * 3 + 0], c0);
        c1 = fmaf(h[j], sW1[j * 3 + 1], c1);
        c2 = fmaf(h[j], sW1[j * 3 + 2], c2);
    }
    c0 = fast_sigmoid(c0);
    c1 = fast_sigmoid(c1);
    c2 = fast_sigmoid(c2);
}

__global__ __launch_bounds__(128) void surfnet_kernel(
    const int*   __restrict__ x,        // [B, N, 2]
    const float* __restrict__ dvec,     // [B, 16]
    const float* __restrict__ grid,     // [TABLE, 4]
    const float* __restrict__ W0,       // [22, 8]
    const float* __restrict__ W1,       // [8, 3]
    float*       __restrict__ sigma_out,// [B, N]
    float*       __restrict__ rgb_out,  // [B, 3]
    int B)
{
    const int tid  = threadIdx.x;
    const int lane = tid & 31;
    const int wid  = tid >> 5;

    __shared__ float sW0g[48];  // W0 rows 16..21, [6][8]
    __shared__ float sW1[24];   // [8][3]

    if (tid < 48)      sW0g[tid]      = W0[128 + tid];   // 16*8 = 128
    else if (tid < 72) sW1[tid - 48]  = W1[tid - 48];
    __syncthreads();

    const int b = blockIdx.x * 4 + wid;   // ray index (one warp per ray)
    if (b >= B) return;

    // per-ray base = d[b] @ W0[0:16,:], computed by lanes 0..7, broadcast
    float base = 0.0f;
    if (lane < 8) {
        const float* dv = dvec + (size_t)b * 16;
        #pragma unroll
        for (int i = 0; i < 16; i++)
            base = fmaf(__ldg(dv + i), __ldg(W0 + i * 8 + lane), base);
    }
    float basev[8];
    #pragma unroll
    for (int j = 0; j < 8; j++)
        basev[j] = __shfl_sync(0xFFFFFFFFu, base, j);

    // ---- gather: 4 consecutive samples per lane -> 8 float4 loads in flight
    const int4* xp = (const int4*)x + (size_t)b * 64 + lane * 2;  // b*256 ints
    const int4 xa = __ldcs(xp);        // {s0.x, s0.y, s1.x, s1.y}
    const int4 xb = __ldcs(xp + 1);    // {s2.x, s2.y, s3.x, s3.y}

    const float4* g4 = (const float4*)grid;
    const float4 fa0 = __ldg(g4 + xa.x), fb0 = __ldg(g4 + xa.y);
    const float4 fa1 = __ldg(g4 + xa.z), fb1 = __ldg(g4 + xa.w);
    const float4 fa2 = __ldg(g4 + xb.x), fb2 = __ldg(g4 + xb.y);
    const float4 fa3 = __ldg(g4 + xb.z), fb3 = __ldg(g4 + xb.w);

    float sg[4];
    sg[0] = fast_sigmoid(fa0.x * fb0.x);
    sg[1] = fast_sigmoid(fa1.x * fb1.x);
    sg[2] = fast_sigmoid(fa2.x * fb2.x);
    sg[3] = fast_sigmoid(fa3.x * fb3.x);

    // coalesced sigma store: 4 consecutive samples = one float4 per lane
    __stcs((float4*)(sigma_out + (size_t)b * 128) + lane,
           make_float4(sg[0], sg[1], sg[2], sg[3]));

    float ca[4], cb[4], cc[4];
    mlp_color(fa0, fb0, basev, sW0g, sW1, ca[0], cb[0], cc[0]);
    mlp_color(fa1, fb1, basev, sW0g, sW1, ca[1], cb[1], cc[1]);
    mlp_color(fa2, fb2, basev, sW0g, sW1, ca[2], cb[2], cc[2]);
    mlp_color(fa3, fb3, basev, sW0g, sW1, ca[3], cb[3], cc[3]);

    // ---- transmittance: serial product within lane, shuffle scan across lanes
    const float om0 = 1.0f - sg[0], om1 = 1.0f - sg[1];
    const float om2 = 1.0f - sg[2], om3 = 1.0f - sg[3];
    float incl = om0 * om1 * om2 * om3;
    #pragma unroll
    for (int off = 1; off < 32; off <<= 1) {
        float v = __shfl_up_sync(0xFFFFFFFFu, incl, off);
        if (lane >= off) incl *= v;
    }
    float T = __shfl_up_sync(0xFFFFFFFFu, incl, 1);
    if (lane == 0) T = 1.0f;

    float r0 = 0.f, r1 = 0.f, r2 = 0.f;
    float w;
    w = T * sg[0]; r0 = fmaf(w, ca[0], r0); r1 = fmaf(w, cb[0], r1); r2 = fmaf(w, cc[0], r2); T *= om0;
    w = T * sg[1]; r0 = fmaf(w, ca[1], r0); r1 = fmaf(w, cb[1], r1); r2 = fmaf(w, cc[1], r2); T *= om1;
    w = T * sg[2]; r0 = fmaf(w, ca[2], r0); r1 = fmaf(w, cb[2], r1); r2 = fmaf(w, cc[2], r2); T *= om2;
    w = T * sg[3]; r0 = fmaf(w, ca[3], r0); r1 = fmaf(w, cb[3], r1); r2 = fmaf(w, cc[3], r2);

    #pragma unroll
    for (int off = 16; off > 0; off >>= 1) {
        r0 += __shfl_down_sync(0xFFFFFFFFu, r0, off);
        r1 += __shfl_down_sync(0xFFFFFFFFu, r1, off);
        r2 += __shfl_down_sync(0xFFFFFFFFu, r2, off);
    }
    if (lane == 0) {
        float* rb = rgb_out + (size_t)b * 3;
        rb[0] = r0; rb[1] = r1; rb[2] = r2;
    }
}

extern "C" void kernel_launch(void* const* d_in, const int* in_sizes, int n_in,
                              void* d_out, int out_size)
{
    const int*   x    = (const int*)d_in[0];
    const float* dv   = (const float*)d_in[1];
    const float* grid = (const float*)d_in[2];
    const float* W0   = (const float*)d_in[3];
    const float* W1   = (const float*)d_in[4];

    const int BN = in_sizes[0] / 2;   // B*N
    const int B  = in_sizes[1] / 16;  // rays

    float* sigma_out = (float*)d_out;
    float* rgb_out   = sigma_out + (size_t)BN;

    // one warp per ray, 4 rays (warps) per 128-thread block
    const int nblk = (B + 3) / 4;
    surfnet_kernel<<<nblk, 128>>>(x, dv, grid, W0, W1, sigma_out, rgb_out, B);
}